// round 3
// baseline (speedup 1.0000x reference)
#include <cuda_runtime.h>
#include <cuda_bf16.h>

// Problem constants (from reference): N=50000 nodes, E=800000 edges,
// IN=512, HID=256, OUT=128.
#define MAX_N 50000
#define IN_DIM 512
#define HID_DIM 256
#define OUT_DIM 128

// ---------------- scratch (static device globals; no allocation) ------------
__device__ int   g_i32flag;                         // 1 if edge_index is int32
__device__ float g_deg [MAX_N];
__device__ float g_dinv[MAX_N];
__device__ float g_h1  [(size_t)MAX_N * HID_DIM];   // x @ W1
__device__ float g_agg1[(size_t)MAX_N * HID_DIM];   // aggregated layer-1
__device__ float g_h2  [(size_t)MAX_N * OUT_DIM];   // relu(agg1+b1) @ W2
__device__ float g_agg2[(size_t)MAX_N * OUT_DIM];   // aggregated layer-2

// ---------------- edge-index dtype dispatch ---------------------------------
// The reference emits int64 edge_index but the harness may deliver int32.
// Detect on-device: read as int64; any value outside [0, Nn) => int32 layout.
// (With random indices in [0,50000), a genuine int32 buffer misread as int64
// fails the range check with probability ~1 per entry; 2048 entries => certain.)
__global__ void detect_idx_kernel(const long long* __restrict__ ei,
                                  int Nn, int E) {
    int bad = 0;
    const int scan = (E < 2048) ? E : 2048;   // stays inside buffer either way
    for (int i = threadIdx.x; i < scan; i += blockDim.x) {
        long long v = ei[i];
        if (v < 0 || v >= (long long)Nn) bad = 1;
    }
    bad = __syncthreads_or(bad);
    if (threadIdx.x == 0) g_i32flag = bad;
}

__device__ __forceinline__ long long load_idx(const void* ei, long long e, int flag) {
    if (flag) return (long long)((const int*)ei)[e];
    return ((const long long*)ei)[e];
}

// ---------------- degree / norm ---------------------------------------------
__global__ void init_deg_kernel(float* deg, int Nn) {
    int i = blockIdx.x * blockDim.x + threadIdx.x;
    if (i < Nn) deg[i] = 1.0f;  // self-loop weight
}

__global__ void deg_accum_kernel(const void* __restrict__ ei,
                                 const float* __restrict__ ew,
                                 float* deg, int E, int Nn) {
    int e = blockIdx.x * blockDim.x + threadIdx.x;
    if (e < E) {
        const int flag = g_i32flag;
        long long c = load_idx(ei, (long long)E + e, flag);  // col = destination
        if (c >= 0 && c < Nn)                                 // safety clamp
            atomicAdd(&deg[c], ew[e]);
    }
}

__global__ void dinv_kernel(const float* __restrict__ deg, float* dinv, int Nn) {
    int i = blockIdx.x * blockDim.x + threadIdx.x;
    if (i < Nn) {
        float d = deg[i];
        dinv[i] = (d > 0.0f) ? rsqrtf(d) : 0.0f;
    }
}

// ---------------- GEMM: C[M,N] = f(A[M,K]) @ B[K,N] (+obias) ----------------
// A-load fusion: a' = A_RELU ? relu(a + abias[k]) : (A_BIAS ? a + abias[k] : a)
// 64x64 block tile, BK=16, 256 threads, 4x4 per-thread register tile.
template<bool A_BIAS, bool A_RELU, bool OUT_BIAS>
__global__ __launch_bounds__(256)
void gemm_kernel(const float* __restrict__ A, const float* __restrict__ B,
                 const float* __restrict__ abias, const float* __restrict__ obias,
                 float* __restrict__ C, int M, int N, int K) {
    constexpr int BM = 64, BN = 64, BK = 16;
    __shared__ float As[BK][BM + 4];  // transposed A tile, padded (pitch%4==0)
    __shared__ float Bs[BK][BN];

    const int m0 = blockIdx.x * BM;
    const int n0 = blockIdx.y * BN;
    const int t  = threadIdx.x;           // 0..255
    const int tx = t & 15;                // N direction (x4)
    const int ty = t >> 4;                // M direction (x4)

    // A-tile load mapping: 64 rows x 16 k -> one float4 per thread
    const int a_row = t >> 2;             // 0..63
    const int a_k4  = (t & 3) << 2;       // 0,4,8,12
    // B-tile load mapping: 16 k x 64 n -> one float4 per thread
    const int b_k   = t >> 4;             // 0..15
    const int b_n4  = (t & 15) << 2;      // 0..60

    float acc[4][4] = {};

    for (int k0 = 0; k0 < K; k0 += BK) {
        // ---- load A tile (transposed into As[k][m]) ----
        float4 av = make_float4(0.f, 0.f, 0.f, 0.f);
        const int gm = m0 + a_row;
        if (gm < M)
            av = *reinterpret_cast<const float4*>(A + (long long)gm * K + k0 + a_k4);
        if (A_BIAS || A_RELU) {
            const float* bb = abias + k0 + a_k4;
            av.x += bb[0]; av.y += bb[1]; av.z += bb[2]; av.w += bb[3];
        }
        if (A_RELU) {
            av.x = fmaxf(av.x, 0.f); av.y = fmaxf(av.y, 0.f);
            av.z = fmaxf(av.z, 0.f); av.w = fmaxf(av.w, 0.f);
        }
        As[a_k4 + 0][a_row] = av.x;
        As[a_k4 + 1][a_row] = av.y;
        As[a_k4 + 2][a_row] = av.z;
        As[a_k4 + 3][a_row] = av.w;

        // ---- load B tile ----
        float4 bv = *reinterpret_cast<const float4*>(
            B + (long long)(k0 + b_k) * N + n0 + b_n4);
        *reinterpret_cast<float4*>(&Bs[b_k][b_n4]) = bv;

        __syncthreads();

        #pragma unroll
        for (int kk = 0; kk < BK; kk++) {
            float4 am = *reinterpret_cast<const float4*>(&As[kk][ty << 2]);
            float4 bn = *reinterpret_cast<const float4*>(&Bs[kk][tx << 2]);
            acc[0][0] += am.x * bn.x; acc[0][1] += am.x * bn.y;
            acc[0][2] += am.x * bn.z; acc[0][3] += am.x * bn.w;
            acc[1][0] += am.y * bn.x; acc[1][1] += am.y * bn.y;
            acc[1][2] += am.y * bn.z; acc[1][3] += am.y * bn.w;
            acc[2][0] += am.z * bn.x; acc[2][1] += am.z * bn.y;
            acc[2][2] += am.z * bn.z; acc[2][3] += am.z * bn.w;
            acc[3][0] += am.w * bn.x; acc[3][1] += am.w * bn.y;
            acc[3][2] += am.w * bn.z; acc[3][3] += am.w * bn.w;
        }
        __syncthreads();
    }

    float4 ob = make_float4(0.f, 0.f, 0.f, 0.f);
    if (OUT_BIAS)
        ob = *reinterpret_cast<const float4*>(obias + n0 + (tx << 2));

    #pragma unroll
    for (int i = 0; i < 4; i++) {
        const int gm = m0 + (ty << 2) + i;
        if (gm < M) {
            float4 o;
            o.x = acc[i][0] + ob.x;
            o.y = acc[i][1] + ob.y;
            o.z = acc[i][2] + ob.z;
            o.w = acc[i][3] + ob.w;
            *reinterpret_cast<float4*>(C + (long long)gm * N + n0 + (tx << 2)) = o;
        }
    }
}

// ---------------- aggregation ------------------------------------------------
// agg[i,:] = h[i,:] * dinv[i]^2  (self-loop term; also initializes the buffer)
template<int DIM>
__global__ void self_init_kernel(const float* __restrict__ h,
                                 const float* __restrict__ dinv,
                                 float* __restrict__ agg, int Nn) {
    const long long idx = (long long)blockIdx.x * blockDim.x + threadIdx.x; // float4 units
    const long long total = (long long)Nn * (DIM / 4);
    if (idx >= total) return;
    const long long node = idx / (DIM / 4);
    float s = dinv[node];
    s = s * s;
    float4 v = reinterpret_cast<const float4*>(h)[idx];
    v.x *= s; v.y *= s; v.z *= s; v.w *= s;
    reinterpret_cast<float4*>(agg)[idx] = v;
}

// One warp per edge: agg[col,:] += coef * h[row,:] via vector reductions.
template<int DIM>
__global__ void edge_agg_kernel(const void* __restrict__ ei,
                                const float* __restrict__ ew,
                                const float* __restrict__ dinv,
                                const float* __restrict__ h,
                                float* __restrict__ agg, int E, int Nn) {
    const int gw   = (int)(((long long)blockIdx.x * blockDim.x + threadIdx.x) >> 5);
    const int lane = threadIdx.x & 31;
    if (gw >= E) return;
    const int flag = g_i32flag;
    const long long r = load_idx(ei, gw, flag);                 // row (source)
    const long long c = load_idx(ei, (long long)E + gw, flag);  // col (dest)
    if (r < 0 || r >= Nn || c < 0 || c >= Nn) return;           // safety clamp
    const float coef = dinv[r] * ew[gw] * dinv[c];

    const float4* hr = reinterpret_cast<const float4*>(h + r * DIM);
    float*        ap = agg + c * DIM;

    #pragma unroll
    for (int ii = 0; ii < DIM / 128; ii++) {
        const int i = lane + ii * 32;                 // float4 index within row
        float4 v = hr[i];
        v.x *= coef; v.y *= coef; v.z *= coef; v.w *= coef;
        asm volatile("red.global.add.v4.f32 [%0], {%1, %2, %3, %4};"
                     :: "l"(ap + i * 4), "f"(v.x), "f"(v.y), "f"(v.z), "f"(v.w)
                     : "memory");
    }
}

// ---------------- launcher ---------------------------------------------------
extern "C" void kernel_launch(void* const* d_in, const int* in_sizes, int n_in,
                              void* d_out, int out_size) {
    const float*      x  = (const float*)     d_in[0];
    const void*       ei =                    d_in[1];   // int32 or int64 (detected)
    const float*      ew = (const float*)     d_in[2];
    const float*      W1 = (const float*)     d_in[3];
    const float*      b1 = (const float*)     d_in[4];
    const float*      W2 = (const float*)     d_in[5];
    const float*      b2 = (const float*)     d_in[6];
    const float*      Wp = (const float*)     d_in[7];
    const float*      bp = (const float*)     d_in[8];
    float*            out = (float*)d_out;

    const int E  = in_sizes[2];            // edge_weight count
    const int Nn = in_sizes[0] / IN_DIM;   // node count

    float *deg, *dinv, *h1, *agg1, *h2, *agg2;
    cudaGetSymbolAddress((void**)&deg,  g_deg);
    cudaGetSymbolAddress((void**)&dinv, g_dinv);
    cudaGetSymbolAddress((void**)&h1,   g_h1);
    cudaGetSymbolAddress((void**)&agg1, g_agg1);
    cudaGetSymbolAddress((void**)&h2,   g_h2);
    cudaGetSymbolAddress((void**)&agg2, g_agg2);

    const int T = 256;

    // ---- edge dtype detection + gcn_norm ----
    detect_idx_kernel<<<1, 256>>>((const long long*)ei, Nn, E);
    init_deg_kernel<<<(Nn + T - 1) / T, T>>>(deg, Nn);
    deg_accum_kernel<<<(E + T - 1) / T, T>>>(ei, ew, deg, E, Nn);
    dinv_kernel<<<(Nn + T - 1) / T, T>>>(deg, dinv, Nn);

    // ---- layer 1: h1 = x @ W1 ; agg1 = norm-aggregate(h1) ----
    {
        dim3 grid((Nn + 63) / 64, HID_DIM / 64);
        gemm_kernel<false, false, false><<<grid, T>>>(x, W1, nullptr, nullptr,
                                                      h1, Nn, HID_DIM, IN_DIM);
    }
    {
        long long tot = (long long)Nn * (HID_DIM / 4);
        self_init_kernel<HID_DIM><<<(unsigned)((tot + T - 1) / T), T>>>(h1, dinv, agg1, Nn);
        long long thr = (long long)E * 32;
        edge_agg_kernel<HID_DIM><<<(unsigned)((thr + T - 1) / T), T>>>(ei, ew, dinv, h1, agg1, E, Nn);
    }

    // ---- layer 2: h2 = relu(agg1 + b1) @ W2 ; agg2 = aggregate(h2) ----
    {
        dim3 grid((Nn + 63) / 64, OUT_DIM / 64);
        gemm_kernel<true, true, false><<<grid, T>>>(agg1, W2, b1, nullptr,
                                                    h2, Nn, OUT_DIM, HID_DIM);
    }
    {
        long long tot = (long long)Nn * (OUT_DIM / 4);
        self_init_kernel<OUT_DIM><<<(unsigned)((tot + T - 1) / T), T>>>(h2, dinv, agg2, Nn);
        long long thr = (long long)E * 32;
        edge_agg_kernel<OUT_DIM><<<(unsigned)((thr + T - 1) / T), T>>>(ei, ew, dinv, h2, agg2, E, Nn);
    }

    // ---- head: out = (agg2 + b2) @ Wp + bp ----
    {
        dim3 grid((Nn + 63) / 64, OUT_DIM / 64);
        gemm_kernel<true, false, true><<<grid, T>>>(agg2, Wp, b2, bp,
                                                    out, Nn, OUT_DIM, OUT_DIM);
    }
}

// round 5
// speedup vs baseline: 1.5223x; 1.5223x over previous
#include <cuda_runtime.h>
#include <cuda_bf16.h>
#include <cstdint>

// Problem constants (from reference): N=50000 nodes, E=800000 edges,
// IN=512, HID=256, OUT=128.
#define MAX_N 50000
#define IN_DIM 512
#define HID_DIM 256
#define OUT_DIM 128

// ---------------- scratch (static device globals; no allocation) ------------
__device__ int   g_i32flag;                         // 1 if edge_index is int32
__device__ float g_deg [MAX_N];
__device__ float g_dinv[MAX_N];
__device__ float g_h1  [(size_t)MAX_N * HID_DIM];   // x @ W1
__device__ float g_agg1[(size_t)MAX_N * HID_DIM];   // aggregated layer-1
__device__ float g_h2  [(size_t)MAX_N * OUT_DIM];   // relu(agg1+b1) @ W2
__device__ float g_agg2[(size_t)MAX_N * OUT_DIM];   // aggregated layer-2

// ---------------- edge-index dtype detect + degree init (merged) ------------
// Reference emits int64 edge_index but the harness delivers int32 (confirmed
// in R3). Keep runtime detection for robustness: read as int64; any value
// outside [0, Nn) => int32 layout. Block 0 detects; all blocks init deg=1.
__global__ void detect_init_kernel(const long long* __restrict__ ei,
                                   float* deg, int Nn, int E) {
    if (blockIdx.x == 0) {
        int bad = 0;
        const int scan = (E < 2048) ? E : 2048;   // stays inside buffer either way
        for (int i = threadIdx.x; i < scan; i += blockDim.x) {
            long long v = ei[i];
            if (v < 0 || v >= (long long)Nn) bad = 1;
        }
        bad = __syncthreads_or(bad);
        if (threadIdx.x == 0) g_i32flag = bad;
    }
    int i = blockIdx.x * blockDim.x + threadIdx.x;
    if (i < Nn) deg[i] = 1.0f;  // self-loop weight
}

__device__ __forceinline__ long long load_idx(const void* ei, long long e, int flag) {
    if (flag) return (long long)((const int*)ei)[e];
    return ((const long long*)ei)[e];
}

// ---------------- degree / norm ---------------------------------------------
__global__ void deg_accum_kernel(const void* __restrict__ ei,
                                 const float* __restrict__ ew,
                                 float* deg, int E, int Nn) {
    int e = blockIdx.x * blockDim.x + threadIdx.x;
    if (e < E) {
        const int flag = g_i32flag;
        long long c = load_idx(ei, (long long)E + e, flag);  // col = destination
        if (c >= 0 && c < Nn)
            atomicAdd(&deg[c], ew[e]);
    }
}

__global__ void dinv_kernel(const float* __restrict__ deg, float* dinv, int Nn) {
    int i = blockIdx.x * blockDim.x + threadIdx.x;
    if (i < Nn) {
        float d = deg[i];
        dinv[i] = (d > 0.0f) ? rsqrtf(d) : 0.0f;
    }
}

// ---------------- tf32 helpers -----------------------------------------------
__device__ __forceinline__ uint32_t f2tf(float x) {
    uint32_t r;
    asm("cvt.rna.tf32.f32 %0, %1;" : "=r"(r) : "f"(x));
    return r;
}

__device__ __forceinline__ void mma_tf32(float* d, const uint32_t* a, const uint32_t* b) {
    asm volatile(
        "mma.sync.aligned.m16n8k8.row.col.f32.tf32.tf32.f32 "
        "{%0,%1,%2,%3}, {%4,%5,%6,%7}, {%8,%9}, {%0,%1,%2,%3};"
        : "+f"(d[0]), "+f"(d[1]), "+f"(d[2]), "+f"(d[3])
        : "r"(a[0]), "r"(a[1]), "r"(a[2]), "r"(a[3]), "r"(b[0]), "r"(b[1]));
}

// ---------------- tensor-core GEMM: C = f(A[M,K]) @ B[K,N] (+obias) ----------
// A-load fusion: a' = A_RELU ? relu(a + abias[k]) : (A_BIAS ? a + abias[k] : a)
// Block tile 128x64x32, 256 threads = 8 warps (4M x 2N), warp tile 32x32 via
// 2x4 m16n8k8 tf32 atoms, fp32 accumulate.
// Smem padding: As stride 36 (frag addr 4g+tg -> 32 distinct banks),
//               Bs stride 72 (frag addr 8tg+g -> 32 distinct banks).
template<bool A_BIAS, bool A_RELU, bool OUT_BIAS>
__global__ __launch_bounds__(256)
void gemm_tf32_kernel(const float* __restrict__ A, const float* __restrict__ B,
                      const float* __restrict__ abias, const float* __restrict__ obias,
                      float* __restrict__ C, int M, int N, int K) {
    constexpr int BM = 128, BN = 64, BK = 32;
    __shared__ uint32_t As[BM][BK + 4];   // stride 36
    __shared__ uint32_t Bs[BK][BN + 8];   // stride 72

    const int t    = threadIdx.x;
    const int wid  = t >> 5;
    const int lane = t & 31;
    const int wm   = (wid >> 1) * 32;     // warp M offset: 0,32,64,96
    const int wn   = (wid & 1) * 32;      // warp N offset: 0,32
    const int g    = lane >> 2;           // groupID 0..7
    const int tg   = lane & 3;            // thread-in-group 0..3
    const int m0   = blockIdx.x * BM;
    const int n0   = blockIdx.y * BN;

    float acc[2][4][4] = {};              // [mtile][ntile][reg]

    for (int k0 = 0; k0 < K; k0 += BK) {
        // ---- load A tile: 128x32 = 1024 float4, 4 per thread ----
        #pragma unroll
        for (int i = 0; i < 4; i++) {
            const int idx = i * 256 + t;
            const int row = idx >> 3;
            const int c4  = (idx & 7) << 2;
            const int gm  = m0 + row;
            float4 v = make_float4(0.f, 0.f, 0.f, 0.f);
            if (gm < M)
                v = *reinterpret_cast<const float4*>(A + (long long)gm * K + k0 + c4);
            if (A_BIAS || A_RELU) {
                const float* bb = abias + k0 + c4;
                v.x += bb[0]; v.y += bb[1]; v.z += bb[2]; v.w += bb[3];
            }
            if (A_RELU) {
                v.x = fmaxf(v.x, 0.f); v.y = fmaxf(v.y, 0.f);
                v.z = fmaxf(v.z, 0.f); v.w = fmaxf(v.w, 0.f);
            }
            As[row][c4 + 0] = f2tf(v.x);
            As[row][c4 + 1] = f2tf(v.y);
            As[row][c4 + 2] = f2tf(v.z);
            As[row][c4 + 3] = f2tf(v.w);
        }
        // ---- load B tile: 32x64 = 512 float4, 2 per thread ----
        #pragma unroll
        for (int i = 0; i < 2; i++) {
            const int idx = i * 256 + t;
            const int kk  = idx >> 4;
            const int c4  = (idx & 15) << 2;
            float4 v = *reinterpret_cast<const float4*>(
                B + (long long)(k0 + kk) * N + n0 + c4);
            Bs[kk][c4 + 0] = f2tf(v.x);
            Bs[kk][c4 + 1] = f2tf(v.y);
            Bs[kk][c4 + 2] = f2tf(v.z);
            Bs[kk][c4 + 3] = f2tf(v.w);
        }
        __syncthreads();

        #pragma unroll
        for (int ks = 0; ks < 4; ks++) {
            const int kb = ks * 8;
            uint32_t afrag[2][4], bfrag[4][2];
            #pragma unroll
            for (int mt = 0; mt < 2; mt++) {
                const int r = wm + mt * 16;
                afrag[mt][0] = As[r + g    ][kb + tg    ];
                afrag[mt][1] = As[r + g + 8][kb + tg    ];
                afrag[mt][2] = As[r + g    ][kb + tg + 4];
                afrag[mt][3] = As[r + g + 8][kb + tg + 4];
            }
            #pragma unroll
            for (int nt = 0; nt < 4; nt++) {
                const int c = wn + nt * 8 + g;
                bfrag[nt][0] = Bs[kb + tg    ][c];
                bfrag[nt][1] = Bs[kb + tg + 4][c];
            }
            #pragma unroll
            for (int mt = 0; mt < 2; mt++)
                #pragma unroll
                for (int nt = 0; nt < 4; nt++)
                    mma_tf32(acc[mt][nt], afrag[mt], bfrag[nt]);
        }
        __syncthreads();
    }

    // ---- epilogue: lane holds rows {wm+mt*16+g, +8}, cols {wn+nt*8+2tg, +1} ----
    #pragma unroll
    for (int mt = 0; mt < 2; mt++) {
        #pragma unroll
        for (int half = 0; half < 2; half++) {      // 0: rows g, 1: rows g+8
            const int gm = m0 + wm + mt * 16 + g + half * 8;
            if (gm >= M) continue;
            #pragma unroll
            for (int nt = 0; nt < 4; nt++) {
                const int col = n0 + wn + nt * 8 + tg * 2;
                float2 o;
                o.x = acc[mt][nt][half * 2 + 0];
                o.y = acc[mt][nt][half * 2 + 1];
                if (OUT_BIAS) {
                    o.x += obias[col];
                    o.y += obias[col + 1];
                }
                *reinterpret_cast<float2*>(C + (long long)gm * N + col) = o;
            }
        }
    }
}

// ---------------- aggregation ------------------------------------------------
// agg[i,:] = h[i,:] * dinv[i]^2  (self-loop term; also initializes the buffer)
template<int DIM>
__global__ void self_init_kernel(const float* __restrict__ h,
                                 const float* __restrict__ dinv,
                                 float* __restrict__ agg, int Nn) {
    const long long idx = (long long)blockIdx.x * blockDim.x + threadIdx.x; // float4 units
    const long long total = (long long)Nn * (DIM / 4);
    if (idx >= total) return;
    const long long node = idx / (DIM / 4);
    float s = dinv[node];
    s = s * s;
    float4 v = reinterpret_cast<const float4*>(h)[idx];
    v.x *= s; v.y *= s; v.z *= s; v.w *= s;
    reinterpret_cast<float4*>(agg)[idx] = v;
}

// One warp per edge: agg[col,:] += coef * h[row,:] via vector reductions.
template<int DIM>
__global__ void edge_agg_kernel(const void* __restrict__ ei,
                                const float* __restrict__ ew,
                                const float* __restrict__ dinv,
                                const float* __restrict__ h,
                                float* __restrict__ agg, int E, int Nn) {
    const int gw   = (int)(((long long)blockIdx.x * blockDim.x + threadIdx.x) >> 5);
    const int lane = threadIdx.x & 31;
    if (gw >= E) return;
    const int flag = g_i32flag;
    const long long r = load_idx(ei, gw, flag);                 // row (source)
    const long long c = load_idx(ei, (long long)E + gw, flag);  // col (dest)
    if (r < 0 || r >= Nn || c < 0 || c >= Nn) return;           // safety clamp
    const float coef = dinv[r] * ew[gw] * dinv[c];

    const float4* hr = reinterpret_cast<const float4*>(h + r * DIM);
    float*        ap = agg + c * DIM;

    #pragma unroll
    for (int ii = 0; ii < DIM / 128; ii++) {
        const int i = lane + ii * 32;                 // float4 index within row
        float4 v = hr[i];
        v.x *= coef; v.y *= coef; v.z *= coef; v.w *= coef;
        asm volatile("red.global.add.v4.f32 [%0], {%1, %2, %3, %4};"
                     :: "l"(ap + i * 4), "f"(v.x), "f"(v.y), "f"(v.z), "f"(v.w)
                     : "memory");
    }
}

// ---------------- launcher ---------------------------------------------------
extern "C" void kernel_launch(void* const* d_in, const int* in_sizes, int n_in,
                              void* d_out, int out_size) {
    const float*      x  = (const float*)     d_in[0];
    const void*       ei =                    d_in[1];   // int32 or int64 (detected)
    const float*      ew = (const float*)     d_in[2];
    const float*      W1 = (const float*)     d_in[3];
    const float*      b1 = (const float*)     d_in[4];
    const float*      W2 = (const float*)     d_in[5];
    const float*      b2 = (const float*)     d_in[6];
    const float*      Wp = (const float*)     d_in[7];
    const float*      bp = (const float*)     d_in[8];
    float*            out = (float*)d_out;

    const int E  = in_sizes[2];            // edge_weight count
    const int Nn = in_sizes[0] / IN_DIM;   // node count

    float *deg, *dinv, *h1, *agg1, *h2, *agg2;
    cudaGetSymbolAddress((void**)&deg,  g_deg);
    cudaGetSymbolAddress((void**)&dinv, g_dinv);
    cudaGetSymbolAddress((void**)&h1,   g_h1);
    cudaGetSymbolAddress((void**)&agg1, g_agg1);
    cudaGetSymbolAddress((void**)&h2,   g_h2);
    cudaGetSymbolAddress((void**)&agg2, g_agg2);

    const int T = 256;

    // ---- launch 0: layer-1 GEMM (independent of norm) ----
    {
        dim3 grid((Nn + 127) / 128, HID_DIM / 64);
        gemm_tf32_kernel<false, false, false><<<grid, T>>>(x, W1, nullptr, nullptr,
                                                           h1, Nn, HID_DIM, IN_DIM);
    }
    // ---- launches 1-3: dtype detect + gcn_norm ----
    detect_init_kernel<<<(Nn + T - 1) / T, T>>>((const long long*)ei, deg, Nn, E);
    deg_accum_kernel<<<(E + T - 1) / T, T>>>(ei, ew, deg, E, Nn);
    dinv_kernel<<<(Nn + T - 1) / T, T>>>(deg, dinv, Nn);

    // ---- launches 4-5: layer-1 aggregation ----
    {
        long long tot = (long long)Nn * (HID_DIM / 4);
        self_init_kernel<HID_DIM><<<(unsigned)((tot + T - 1) / T), T>>>(h1, dinv, agg1, Nn);
        long long thr = (long long)E * 32;
        edge_agg_kernel<HID_DIM><<<(unsigned)((thr + T - 1) / T), T>>>(ei, ew, dinv, h1, agg1, E, Nn);
    }

    // ---- layer 2: h2 = relu(agg1 + b1) @ W2 ; agg2 = aggregate(h2) ----
    {
        dim3 grid((Nn + 127) / 128, OUT_DIM / 64);
        gemm_tf32_kernel<true, true, false><<<grid, T>>>(agg1, W2, b1, nullptr,
                                                         h2, Nn, OUT_DIM, HID_DIM);
    }
    {
        long long tot = (long long)Nn * (OUT_DIM / 4);
        self_init_kernel<OUT_DIM><<<(unsigned)((tot + T - 1) / T), T>>>(h2, dinv, agg2, Nn);
        long long thr = (long long)E * 32;
        edge_agg_kernel<OUT_DIM><<<(unsigned)((thr + T - 1) / T), T>>>(ei, ew, dinv, h2, agg2, E, Nn);
    }

    // ---- head: out = (agg2 + b2) @ Wp + bp ----
    {
        dim3 grid((Nn + 127) / 128, OUT_DIM / 64);
        gemm_tf32_kernel<true, false, true><<<grid, T>>>(agg2, Wp, b2, bp,
                                                         out, Nn, OUT_DIM, OUT_DIM);
    }
}